// round 3
// baseline (speedup 1.0000x reference)
#include <cuda_runtime.h>
#include <math.h>

// Problem constants (fixed by the reference).
#define BB 64
#define TT 188
#define VV 32000
#define ROWS (BB * TT)
#define BETA 2.0f

#define ROW_THREADS 512
#define ROW_WARPS (ROW_THREADS / 32)

// Fixed-point scale for deterministic (order-independent) atomic accumulation.
#define FP_SCALE 4294967296.0   // 2^32

// Scratch (device globals; zero-initialized at module load, reset by last block
// each launch so graph replays see a clean state).
__device__ unsigned long long g_acc;    // fixed-point sum of row losses
__device__ unsigned int       g_done;   // completion counter

// One block per (b, t) row. Streams V=32000 floats with float4 loads,
// computes argmax (first-index tie-break, matching jnp.argmax), then the
// row loss. Thread 0 accumulates into a single fixed-point global via
// atomicAdd (integer adds -> bit-deterministic). The last block to finish
// converts and writes the output, then resets scratch for the next replay.
__global__ __launch_bounds__(ROW_THREADS)
void fused_loss_kernel(const float* __restrict__ scores,
                       const int*   __restrict__ targets,
                       const int*   __restrict__ lengths,
                       float*       __restrict__ out) {
    const int row = blockIdx.x;
    const int b = row / TT;
    const int t = row % TT;
    const int tid  = threadIdx.x;
    const int lane = tid & 31;
    const int wid  = tid >> 5;

    float rowloss = 0.0f;   // only meaningful in thread 0

    if (t < __ldg(&lengths[b])) {
        const size_t base = (size_t)row * VV;
        const float4* __restrict__ p = (const float4*)(scores + base);

        float maxv = -1.0f;   // scores are strictly positive probabilities
        int   maxi = VV;

        // 8000 float4 per row, strided across 512 threads.
        #pragma unroll 4
        for (int i = tid; i < VV / 4; i += ROW_THREADS) {
            float4 v = p[i];
            const int idx = i * 4;
            // Within-thread indices strictly increase -> '>' gives first-index tie-break.
            if (v.x > maxv) { maxv = v.x; maxi = idx;     }
            if (v.y > maxv) { maxv = v.y; maxi = idx + 1; }
            if (v.z > maxv) { maxv = v.z; maxi = idx + 2; }
            if (v.w > maxv) { maxv = v.w; maxi = idx + 3; }
        }

        // Warp reduction: keep max; on tie keep smaller index.
        #pragma unroll
        for (int off = 16; off > 0; off >>= 1) {
            float ov = __shfl_down_sync(0xffffffffu, maxv, off);
            int   oi = __shfl_down_sync(0xffffffffu, maxi, off);
            if (ov > maxv || (ov == maxv && oi < maxi)) { maxv = ov; maxi = oi; }
        }

        __shared__ float s_val[ROW_WARPS];
        __shared__ int   s_idx[ROW_WARPS];
        if (lane == 0) { s_val[wid] = maxv; s_idx[wid] = maxi; }
        __syncthreads();

        if (wid == 0) {
            maxv = (lane < ROW_WARPS) ? s_val[lane] : -1.0f;
            maxi = (lane < ROW_WARPS) ? s_idx[lane] : VV;
            #pragma unroll
            for (int off = 8; off > 0; off >>= 1) {
                float ov = __shfl_down_sync(0xffffffffu, maxv, off);
                int   oi = __shfl_down_sync(0xffffffffu, maxi, off);
                if (ov > maxv || (ov == maxv && oi < maxi)) { maxv = ov; maxi = oi; }
            }
            if (lane == 0) {
                const int target = __ldg(&targets[row]);
                const float gathered = __ldg(&scores[base + (size_t)target]);
                const float w = (maxi == target && target != 0) ? BETA : 1.0f;
                rowloss = -w * logf(gathered);
            }
        }
    }

    // ---- single-thread tail: deterministic fixed-point accumulation ----
    if (tid == 0) {
        if (rowloss > 0.0f) {
            unsigned long long fx =
                (unsigned long long)((double)rowloss * FP_SCALE);
            atomicAdd(&g_acc, fx);
        }
        __threadfence();   // order my g_acc add before my counter bump (1 warp only)
        unsigned int c = atomicAdd(&g_done, 1u);
        if (c == (unsigned int)(ROWS - 1)) {
            // All other blocks have added (their fence+bump precede this point).
            unsigned long long total = atomicAdd(&g_acc, 0ull);  // coherent read
            out[0] = (float)(((double)total / FP_SCALE) / (double)BB);
            // Reset scratch for the next graph replay.
            g_acc  = 0ull;
            g_done = 0u;
        }
    }
}

extern "C" void kernel_launch(void* const* d_in, const int* in_sizes, int n_in,
                              void* d_out, int out_size) {
    const float* scores  = (const float*)d_in[0];  // [B,T,V] fp32
    const int*   targets = (const int*)  d_in[1];  // [B,T]   int32
    const int*   lengths = (const int*)  d_in[2];  // [B]     int32
    float* out = (float*)d_out;                    // [1]     fp32

    fused_loss_kernel<<<ROWS, ROW_THREADS>>>(scores, targets, lengths, out);
}

// round 4
// speedup vs baseline: 1.0868x; 1.0868x over previous
#include <cuda_runtime.h>
#include <math.h>

// Problem constants (fixed by the reference).
#define BB 64
#define TT 188
#define VV 32000
#define ROWS (BB * TT)
#define BETA 2.0f

#define ROW_THREADS 512
#define ROW_WARPS (ROW_THREADS / 32)

// Fixed-point scale for deterministic (order-independent) atomic accumulation.
#define FP_SCALE 4294967296.0   // 2^32

// Scratch (device global; zero-initialized at module load, reset by the
// finalize kernel each launch so graph replays see a clean state).
__device__ unsigned long long g_acc;

// One block per (b, t) row. Streams V=32000 floats with streaming float4
// loads, computes argmax (first-index tie-break, matching jnp.argmax), then
// the row loss. Thread 0 fires ONE no-return atomicAdd (REDG) of the
// fixed-point row loss -- integer adds are order-independent, so the result
// is bit-deterministic. No fence, no counter: the finalize kernel's launch
// boundary provides the ordering.
__global__ __launch_bounds__(ROW_THREADS)
void row_loss_kernel(const float* __restrict__ scores,
                     const int*   __restrict__ targets,
                     const int*   __restrict__ lengths) {
    const int row = blockIdx.x;
    const int b = row / TT;
    const int t = row % TT;
    const int tid  = threadIdx.x;
    const int lane = tid & 31;
    const int wid  = tid >> 5;

    // Masked rows contribute 0: skip the 128 KB read entirely.
    if (t >= __ldg(&lengths[b])) return;

    const size_t base = (size_t)row * VV;
    const float4* __restrict__ p = (const float4*)(scores + base);

    float maxv = -1.0f;   // scores are strictly positive probabilities
    int   maxi = VV;

    // 8000 float4 per row, strided across 512 threads. Streaming loads:
    // each sector is touched exactly once.
    #pragma unroll 4
    for (int i = tid; i < VV / 4; i += ROW_THREADS) {
        float4 v = __ldcs(&p[i]);
        const int idx = i * 4;
        // Within-thread indices strictly increase -> '>' gives first-index tie-break.
        if (v.x > maxv) { maxv = v.x; maxi = idx;     }
        if (v.y > maxv) { maxv = v.y; maxi = idx + 1; }
        if (v.z > maxv) { maxv = v.z; maxi = idx + 2; }
        if (v.w > maxv) { maxv = v.w; maxi = idx + 3; }
    }

    // Warp reduction: keep max; on tie keep smaller index.
    #pragma unroll
    for (int off = 16; off > 0; off >>= 1) {
        float ov = __shfl_down_sync(0xffffffffu, maxv, off);
        int   oi = __shfl_down_sync(0xffffffffu, maxi, off);
        if (ov > maxv || (ov == maxv && oi < maxi)) { maxv = ov; maxi = oi; }
    }

    __shared__ float s_val[ROW_WARPS];
    __shared__ int   s_idx[ROW_WARPS];
    if (lane == 0) { s_val[wid] = maxv; s_idx[wid] = maxi; }
    __syncthreads();

    if (wid == 0) {
        maxv = (lane < ROW_WARPS) ? s_val[lane] : -1.0f;
        maxi = (lane < ROW_WARPS) ? s_idx[lane] : VV;
        #pragma unroll
        for (int off = 8; off > 0; off >>= 1) {
            float ov = __shfl_down_sync(0xffffffffu, maxv, off);
            int   oi = __shfl_down_sync(0xffffffffu, maxi, off);
            if (ov > maxv || (ov == maxv && oi < maxi)) { maxv = ov; maxi = oi; }
        }
        if (lane == 0) {
            const int target = __ldg(&targets[row]);
            const float gathered = __ldg(&scores[base + (size_t)target]);
            const float w = (maxi == target && target != 0) ? BETA : 1.0f;
            const float rowloss = -w * logf(gathered);
            // Fire-and-forget (return value unused -> REDG, off critical path).
            atomicAdd(&g_acc, (unsigned long long)((double)rowloss * FP_SCALE));
        }
    }
}

// Finalize: convert fixed-point sum, write output, reset scratch for replay.
__global__ void finalize_kernel(float* __restrict__ out) {
    if (threadIdx.x == 0) {
        out[0] = (float)(((double)g_acc / FP_SCALE) / (double)BB);
        g_acc = 0ull;
    }
}

extern "C" void kernel_launch(void* const* d_in, const int* in_sizes, int n_in,
                              void* d_out, int out_size) {
    const float* scores  = (const float*)d_in[0];  // [B,T,V] fp32
    const int*   targets = (const int*)  d_in[1];  // [B,T]   int32
    const int*   lengths = (const int*)  d_in[2];  // [B]     int32
    float* out = (float*)d_out;                    // [1]     fp32

    row_loss_kernel<<<ROWS, ROW_THREADS>>>(scores, targets, lengths);
    finalize_kernel<<<1, 32>>>(out);
}

// round 5
// speedup vs baseline: 1.1270x; 1.0369x over previous
#include <cuda_runtime.h>
#include <math.h>

// Problem constants (fixed by the reference).
#define BB 64
#define TT 188
#define VV 32000
#define ROWS (BB * TT)
#define BETA 2.0f

#define ROW_THREADS 512
#define ROW_WARPS (ROW_THREADS / 32)

// Fixed-point scale for deterministic (order-independent) atomic accumulation.
#define FP_SCALE 4294967296.0   // 2^32

// Scratch (device global; zero-initialized at module load, reset by the
// finalize kernel each launch so graph replays see a clean state).
__device__ unsigned long long g_acc;

// One block per (b, t) row. Streams V=32000 floats with streaming float4
// loads, computes argmax (first-index tie-break, matching jnp.argmax), then
// the row loss. Thread 0 fires ONE no-return atomicAdd (REDG) of the
// fixed-point row loss -- integer adds are order-independent, so the result
// is bit-deterministic. No fence, no counter: the PDL grid-dependency sync
// in the finalize kernel provides the ordering.
__global__ __launch_bounds__(ROW_THREADS)
void row_loss_kernel(const float* __restrict__ scores,
                     const int*   __restrict__ targets,
                     const int*   __restrict__ lengths) {
    const int row = blockIdx.x;
    const int b = row / TT;
    const int t = row % TT;
    const int tid  = threadIdx.x;
    const int lane = tid & 31;
    const int wid  = tid >> 5;

    // Masked rows contribute 0: skip the 128 KB read entirely.
    if (t >= __ldg(&lengths[b])) return;

    const size_t base = (size_t)row * VV;
    const float4* __restrict__ p = (const float4*)(scores + base);

    float maxv = -1.0f;   // scores are strictly positive probabilities
    int   maxi = VV;

    // 8000 float4 per row, strided across 512 threads. Streaming loads:
    // each sector is touched exactly once.
    #pragma unroll 4
    for (int i = tid; i < VV / 4; i += ROW_THREADS) {
        float4 v = __ldcs(&p[i]);
        const int idx = i * 4;
        // Within-thread indices strictly increase -> '>' gives first-index tie-break.
        if (v.x > maxv) { maxv = v.x; maxi = idx;     }
        if (v.y > maxv) { maxv = v.y; maxi = idx + 1; }
        if (v.z > maxv) { maxv = v.z; maxi = idx + 2; }
        if (v.w > maxv) { maxv = v.w; maxi = idx + 3; }
    }

    // Warp reduction: keep max; on tie keep smaller index.
    #pragma unroll
    for (int off = 16; off > 0; off >>= 1) {
        float ov = __shfl_down_sync(0xffffffffu, maxv, off);
        int   oi = __shfl_down_sync(0xffffffffu, maxi, off);
        if (ov > maxv || (ov == maxv && oi < maxi)) { maxv = ov; maxi = oi; }
    }

    __shared__ float s_val[ROW_WARPS];
    __shared__ int   s_idx[ROW_WARPS];
    if (lane == 0) { s_val[wid] = maxv; s_idx[wid] = maxi; }
    __syncthreads();

    if (wid == 0) {
        maxv = (lane < ROW_WARPS) ? s_val[lane] : -1.0f;
        maxi = (lane < ROW_WARPS) ? s_idx[lane] : VV;
        #pragma unroll
        for (int off = 8; off > 0; off >>= 1) {
            float ov = __shfl_down_sync(0xffffffffu, maxv, off);
            int   oi = __shfl_down_sync(0xffffffffu, maxi, off);
            if (ov > maxv || (ov == maxv && oi < maxi)) { maxv = ov; maxi = oi; }
        }
        if (lane == 0) {
            const int target = __ldg(&targets[row]);
            const float gathered = __ldg(&scores[base + (size_t)target]);
            const float w = (maxi == target && target != 0) ? BETA : 1.0f;
            const float rowloss = -w * logf(gathered);
            // Fire-and-forget (return value unused -> REDG, off critical path).
            atomicAdd(&g_acc, (unsigned long long)((double)rowloss * FP_SCALE));
        }
    }
}

// Finalize: launched with programmatic dependent launch so it is resident
// while the primary grid drains. The grid-dependency sync guarantees all of
// row_loss_kernel's memory operations (the REDG adds) are visible before we
// read the accumulator. Converts fixed-point sum, writes output, resets
// scratch for the next graph replay.
__global__ void finalize_kernel(float* __restrict__ out) {
    cudaGridDependencySynchronize();
    if (threadIdx.x == 0) {
        out[0] = (float)(((double)g_acc / FP_SCALE) / (double)BB);
        g_acc = 0ull;
    }
}

extern "C" void kernel_launch(void* const* d_in, const int* in_sizes, int n_in,
                              void* d_out, int out_size) {
    const float* scores  = (const float*)d_in[0];  // [B,T,V] fp32
    const int*   targets = (const int*)  d_in[1];  // [B,T]   int32
    const int*   lengths = (const int*)  d_in[2];  // [B]     int32
    float* out = (float*)d_out;                    // [1]     fp32

    row_loss_kernel<<<ROWS, ROW_THREADS>>>(scores, targets, lengths);

    // PDL launch of the finalize kernel: overlaps its launch latency with the
    // primary kernel's tail; cudaGridDependencySynchronize() inside enforces
    // correctness ordering.
    cudaLaunchConfig_t cfg = {};
    cfg.gridDim  = dim3(1, 1, 1);
    cfg.blockDim = dim3(32, 1, 1);
    cfg.dynamicSmemBytes = 0;
    cfg.stream = 0;
    cudaLaunchAttribute attrs[1];
    attrs[0].id = cudaLaunchAttributeProgrammaticStreamSerialization;
    attrs[0].val.programmaticStreamSerializationAllowed = 1;
    cfg.attrs = attrs;
    cfg.numAttrs = 1;
    cudaLaunchKernelEx(&cfg, finalize_kernel, out);
}